// round 1
// baseline (speedup 1.0000x reference)
#include <cuda_runtime.h>
#include <math.h>

#define BATCH   4096
#define IN_DIM  512
#define NH      32
#define OUT_DIM 512

#define BM 128
#define BN 128
#define BK 64      // one input feature: 32 harmonics x {cos,sin}
#define THREADS 256

typedef unsigned long long u64;

// Packed f32x2 FMA (sm_100+/sm_103a): d = a*b + c on two fp32 lanes.
__device__ __forceinline__ u64 fma2(u64 a, u64 b, u64 c) {
    u64 d;
    asm("fma.rn.f32x2 %0, %1, %2, %3;" : "=l"(d) : "l"(a), "l"(b), "l"(c));
    return d;
}
__device__ __forceinline__ u64 pack_dup(float a) {
    u64 d;
    asm("mov.b64 %0, {%1, %1};" : "=l"(d) : "f"(a));
    return d;
}
__device__ __forceinline__ float2 unpack2(u64 v) {
    float2 r;
    asm("mov.b64 {%0, %1}, %2;" : "=f"(r.x), "=f"(r.y) : "l"(v));
    return r;
}

__global__ void __launch_bounds__(THREADS, 1)
fourier_kan_kernel(const float* __restrict__ X,     // [BATCH, IN_DIM]
                   const float* __restrict__ W,     // [IN_DIM*64, OUT_DIM] (= fourier_coeffs flat)
                   const float* __restrict__ bias,  // [OUT_DIM]
                   float* __restrict__ out)         // [BATCH, OUT_DIM]
{
    extern __shared__ float smem[];
    float* As = smem;             // [BK][BM]
    float* Ws = smem + BK * BM;   // [BK][BN]

    const int tid = threadIdx.x;
    const int tx  = tid & 15;     // N direction (8 cols each)
    const int ty  = tid >> 4;     // M direction (8 rows each)
    const int bn0 = blockIdx.x * BN;
    const int bm0 = blockIdx.y * BM;

    u64 acc[8][4];
    #pragma unroll
    for (int mi = 0; mi < 8; ++mi)
        #pragma unroll
        for (int nj = 0; nj < 4; ++nj) acc[mi][nj] = 0ull;  // packed (0.f, 0.f)

    const int wrow = tid >> 5;          // 0..7
    const int wcol = (tid & 31) << 2;   // 0,4,...,124

    const float* xrow = X + (size_t)(bm0 + (tid < BM ? tid : 0)) * IN_DIM;

    for (int i = 0; i < IN_DIM; ++i) {
        // ---- load W chunk [64 x BN] into SMEM (coalesced float4) ----
        const float* Wg = W + ((size_t)i * BK) * OUT_DIM + bn0;
        #pragma unroll
        for (int p = 0; p < 8; ++p) {
            int r = (p << 3) + wrow;
            float4 v = *reinterpret_cast<const float4*>(Wg + (size_t)r * OUT_DIM + wcol);
            *reinterpret_cast<float4*>(&Ws[r * BN + wcol]) = v;
        }

        // ---- generate A chunk: cos/sin harmonics via rotation recurrence ----
        if (tid < BM) {
            float x = xrow[i];
            float s1, c1;
            sincosf(x, &s1, &c1);
            float c = c1, s = s1;
            #pragma unroll
            for (int g = 0; g < NH; ++g) {
                As[(2 * g)     * BM + tid] = c;
                As[(2 * g + 1) * BM + tid] = s;
                float cn = fmaf(c, c1, -s * s1);
                float sn = fmaf(s, c1,  c * s1);
                c = cn; s = sn;
            }
        }
        __syncthreads();

        // ---- 128x128x64 tile product, packed f32x2 MACs ----
        #pragma unroll 8
        for (int k = 0; k < BK; ++k) {
            float4 a0 = *reinterpret_cast<const float4*>(&As[k * BM + ty * 8]);
            float4 a1 = *reinterpret_cast<const float4*>(&As[k * BM + ty * 8 + 4]);
            ulonglong2 w01 = *reinterpret_cast<const ulonglong2*>(&Ws[k * BN + tx * 8]);
            ulonglong2 w23 = *reinterpret_cast<const ulonglong2*>(&Ws[k * BN + tx * 8 + 4]);
            u64 wp[4] = {w01.x, w01.y, w23.x, w23.y};
            float av[8] = {a0.x, a0.y, a0.z, a0.w, a1.x, a1.y, a1.z, a1.w};
            #pragma unroll
            for (int mi = 0; mi < 8; ++mi) {
                u64 ap = pack_dup(av[mi]);
                #pragma unroll
                for (int nj = 0; nj < 4; ++nj)
                    acc[mi][nj] = fma2(ap, wp[nj], acc[mi][nj]);
            }
        }
        __syncthreads();
    }

    // ---- epilogue: add bias, store ----
    #pragma unroll
    for (int mi = 0; mi < 8; ++mi) {
        int row = bm0 + ty * 8 + mi;
        float* orow = out + (size_t)row * OUT_DIM + bn0 + tx * 8;
        const float* brow = bias + bn0 + tx * 8;
        #pragma unroll
        for (int nj = 0; nj < 4; ++nj) {
            float2 v = unpack2(acc[mi][nj]);
            v.x += brow[2 * nj];
            v.y += brow[2 * nj + 1];
            *reinterpret_cast<float2*>(orow + 2 * nj) = v;
        }
    }
}

extern "C" void kernel_launch(void* const* d_in, const int* in_sizes, int n_in,
                              void* d_out, int out_size) {
    const float* X    = (const float*)d_in[0];
    const float* W    = (const float*)d_in[1];  // fourier_coeffs [512,32,2,512] flat
    const float* bias = (const float*)d_in[2];
    float* out = (float*)d_out;

    (void)in_sizes; (void)n_in; (void)out_size;

    // 64 KB dynamic SMEM (> 48 KB default) — attribute is sticky per function.
    cudaFuncSetAttribute(fourier_kan_kernel,
                         cudaFuncAttributeMaxDynamicSharedMemorySize, 64 * 1024);

    dim3 grid(OUT_DIM / BN, BATCH / BM);
    fourier_kan_kernel<<<grid, THREADS, 64 * 1024>>>(X, W, bias, out);
}

// round 3
// speedup vs baseline: 4.6593x; 4.6593x over previous
#include <cuda_runtime.h>
#include <cuda_fp16.h>
#include <cstdint>
#include <math.h>

#define BATCH   4096
#define IN_DIM  512
#define NH      32
#define OUT_DIM 512
#define KTOT    (IN_DIM * NH * 2)   // 32768

#define BM 128
#define BN 128
#define BK 64          // one input feature per K-iter: 32 harmonics x {cos,sin}
#define THREADS 256
#define STAGE_SZ 32768              // A tile 16KB + B tile 16KB
#define SM_TOTAL (2 * STAGE_SZ + 512)

// transposed fp16 weights: [OUT_DIM n][KTOT k]
__device__ __half g_Wt[(size_t)OUT_DIM * KTOT];   // 32 MB

__device__ __forceinline__ uint32_t smem_u32(const void* p) {
    uint32_t a;
    asm("{ .reg .u64 t; cvta.to.shared.u64 t, %1; cvt.u32.u64 %0, t; }" : "=r"(a) : "l"(p));
    return a;
}

// ---------------- kernel 1: transpose + fp16 convert of W ----------------
__global__ void __launch_bounds__(256)
w_prep_kernel(const float* __restrict__ W) {      // W: [KTOT, OUT_DIM]
    __shared__ float t[32][33];
    int k0 = blockIdx.x * 32;
    int n0 = blockIdx.y * 32;
    int tx = threadIdx.x, ty = threadIdx.y;       // block (32, 8)
    #pragma unroll
    for (int r = 0; r < 4; ++r)
        t[ty + 8 * r][tx] = W[(size_t)(k0 + ty + 8 * r) * OUT_DIM + n0 + tx];
    __syncthreads();
    #pragma unroll
    for (int r = 0; r < 4; ++r) {
        float v = t[tx][ty + 8 * r];
        g_Wt[(size_t)(n0 + ty + 8 * r) * KTOT + k0 + tx] = __float2half_rn(v);
    }
}

// ---------------- kernel 2: fused trig-gen + HMMA GEMM ----------------
// SMEM: stage s at s*32KB: A [128m][64k] half (swizzled), B [128n][64k] half (swizzled)
// bias tile (128 f32) at 64KB.
__global__ void __launch_bounds__(THREADS, 1)
fkan_hmma_kernel(const float* __restrict__ X,
                 const float* __restrict__ bias,
                 float* __restrict__ out)
{
    extern __shared__ char smem[];
    const uint32_t sb = smem_u32(smem);
    const int tid = threadIdx.x;
    const int wid = tid >> 5, l = tid & 31;
    const int wm = wid & 1, wn = wid >> 1;        // warp tile: 64m x 32n
    const int bn0 = blockIdx.x * BN;
    const int bm0 = blockIdx.y * BM;

    if (tid < BN)
        ((float*)(smem + 2 * STAGE_SZ))[tid] = bias[bn0 + tid];

    // lane-constant ldmatrix address components
    const int ar  = ((l >> 3) & 1) * 8 + (l & 7); // A: tile row-in-16
    const int akx = (l >> 4) << 4;                // A: k-half select (bytes)
    const int br  = ((l >> 4) & 1) * 8 + (l & 7); // B: tile row-in-16 (n)
    const int bkx = ((l >> 3) & 1) << 4;          // B: k-half select (bytes)
    const int sw  = (l & 7) << 4;                 // XOR swizzle term

    // A-gen mapping: 2 threads per m-row, 16 harmonics each
    const int am = tid >> 1, ah = tid & 1;
    const float* xrow = X + (size_t)(bm0 + am) * IN_DIM;
    // B-load mapping: 2 threads per n-row, 64B each
    const int brow = tid >> 1, bhalf = (tid & 1) * 64;
    const char* wsrc0 = (const char*)g_Wt + ((size_t)(bn0 + brow) * KTOT) * 2 + bhalf;

    float acc[4][4][4];
    #pragma unroll
    for (int mf = 0; mf < 4; ++mf)
        #pragma unroll
        for (int nf = 0; nf < 4; ++nf)
            #pragma unroll
            for (int q = 0; q < 4; ++q) acc[mf][nf][q] = 0.f;

    auto fill = [&](int s, int i) {
        // ---- B tile via cp.async (Wt rows, swizzled 16B granules) ----
        const char* src = wsrc0 + (size_t)i * 128;   // i*64 halves
        uint32_t dst = sb + s * STAGE_SZ + 16384 + brow * 128;
        uint32_t bswz = (brow & 7) << 4;
        #pragma unroll
        for (int j = 0; j < 4; ++j) {
            uint32_t d = dst + ((bhalf + 16 * j) ^ bswz);
            asm volatile("cp.async.cg.shared.global [%0], [%1], 16;"
                         :: "r"(d), "l"(src + 16 * j) : "memory");
        }
        asm volatile("cp.async.commit_group;" ::: "memory");

        // ---- A tile: cos/sin harmonics via rotation recurrence ----
        float x = xrow[i];
        float s1, c1, cv, sv;
        sincosf(x, &s1, &c1);
        if (ah == 0) { cv = c1; sv = s1; }
        else         { sincosf(17.0f * x, &sv, &cv); }
        uint32_t abase = sb + s * STAGE_SZ + am * 128;
        uint32_t aswz = (am & 7) << 4;
        #pragma unroll
        for (int g = 0; g < 16; ++g) {
            __half2 p = __floats2half2_rn(cv, sv);   // lo=cos(k=2h), hi=sin(k=2h+1)
            uint32_t kb = 4 * (ah * 16 + g);
            asm volatile("st.shared.b32 [%0], %1;"
                         :: "r"(abase + (kb ^ aswz)), "r"(*(uint32_t*)&p) : "memory");
            float cn = fmaf(cv, c1, -sv * s1);
            float sn = fmaf(sv, c1,  cv * s1);
            cv = cn; sv = sn;
        }
    };

    auto domma = [&](int s) {
        uint32_t sA = sb + s * STAGE_SZ;
        uint32_t sB = sA + 16384;
        #pragma unroll
        for (int kk = 0; kk < 4; ++kk) {
            const int kbase = kk * 32;
            uint32_t a[4][4];
            #pragma unroll
            for (int mf = 0; mf < 4; ++mf) {
                uint32_t addr = sA + (uint32_t)(wm * 64 + mf * 16 + ar) * 128
                              + (uint32_t)((kbase + akx) ^ sw);
                asm volatile("ldmatrix.sync.aligned.m8n8.x4.shared.b16 {%0,%1,%2,%3}, [%4];"
                    : "=r"(a[mf][0]), "=r"(a[mf][1]), "=r"(a[mf][2]), "=r"(a[mf][3])
                    : "r"(addr));
            }
            uint32_t b[4][2];
            #pragma unroll
            for (int pj = 0; pj < 2; ++pj) {
                uint32_t addr = sB + (uint32_t)(wn * 32 + pj * 16 + br) * 128
                              + (uint32_t)((kbase + bkx) ^ sw);
                uint32_t r0, r1, r2, r3;
                asm volatile("ldmatrix.sync.aligned.m8n8.x4.shared.b16 {%0,%1,%2,%3}, [%4];"
                    : "=r"(r0), "=r"(r1), "=r"(r2), "=r"(r3) : "r"(addr));
                b[2 * pj][0] = r0;     b[2 * pj][1] = r1;
                b[2 * pj + 1][0] = r2; b[2 * pj + 1][1] = r3;
            }
            #pragma unroll
            for (int mf = 0; mf < 4; ++mf)
                #pragma unroll
                for (int nf = 0; nf < 4; ++nf)
                    asm volatile(
                        "mma.sync.aligned.m16n8k16.row.col.f32.f16.f16.f32 "
                        "{%0,%1,%2,%3}, {%4,%5,%6,%7}, {%8,%9}, {%0,%1,%2,%3};"
                        : "+f"(acc[mf][nf][0]), "+f"(acc[mf][nf][1]),
                          "+f"(acc[mf][nf][2]), "+f"(acc[mf][nf][3])
                        : "r"(a[mf][0]), "r"(a[mf][1]), "r"(a[mf][2]), "r"(a[mf][3]),
                          "r"(b[nf][0]), "r"(b[nf][1]));
        }
    };

    // prologue: fill stage 0
    fill(0, 0);
    asm volatile("cp.async.wait_group 0;" ::: "memory");
    __syncthreads();

    for (int i = 0; i < IN_DIM; ++i) {
        const int s = i & 1;
        if (i + 1 < IN_DIM) fill(s ^ 1, i + 1);
        domma(s);
        asm volatile("cp.async.wait_group 0;" ::: "memory");
        __syncthreads();
    }

    // ---- epilogue: acc + bias -> out ----
    const float* biasS = (const float*)(smem + 2 * STAGE_SZ);
    #pragma unroll
    for (int mf = 0; mf < 4; ++mf) {
        int m = bm0 + wm * 64 + mf * 16 + (l >> 2);
        #pragma unroll
        for (int nf = 0; nf < 4; ++nf) {
            int nc = wn * 32 + nf * 8 + 2 * (l & 3);
            int n = bn0 + nc;
            float2 v0 = { acc[mf][nf][0] + biasS[nc],
                          acc[mf][nf][1] + biasS[nc + 1] };
            float2 v1 = { acc[mf][nf][2] + biasS[nc],
                          acc[mf][nf][3] + biasS[nc + 1] };
            *(float2*)(out + (size_t)m * OUT_DIM + n)       = v0;
            *(float2*)(out + (size_t)(m + 8) * OUT_DIM + n) = v1;
        }
    }
}

// ---------------- launcher ----------------
extern "C" void kernel_launch(void* const* d_in, const int* in_sizes, int n_in,
                              void* d_out, int out_size) {
    const float* X    = (const float*)d_in[0];
    const float* W    = (const float*)d_in[1];   // [512,32,2,512] flat = [KTOT, OUT_DIM]
    const float* bias = (const float*)d_in[2];
    float* out = (float*)d_out;
    (void)in_sizes; (void)n_in; (void)out_size;

    dim3 pgrid(KTOT / 32, OUT_DIM / 32);
    w_prep_kernel<<<pgrid, dim3(32, 8)>>>(W);

    cudaFuncSetAttribute(fkan_hmma_kernel,
                         cudaFuncAttributeMaxDynamicSharedMemorySize, SM_TOTAL);
    dim3 grid(OUT_DIM / BN, BATCH / BM);
    fkan_hmma_kernel<<<grid, THREADS, SM_TOTAL>>>(X, bias, out);
}

// round 4
// speedup vs baseline: 4.7023x; 1.0092x over previous
#include <cuda_runtime.h>
#include <cuda_fp16.h>
#include <cstdint>
#include <math.h>

#define BATCH   4096
#define IN_DIM  512
#define NH      32
#define OUT_DIM 512
#define KTOT    (IN_DIM * NH * 2)   // 32768

#define BM 128
#define BN 128
#define BK 64
#define THREADS 256
#define STAGE_SZ 32768              // A 16KB + B 16KB
#define SM_TOTAL (2 * STAGE_SZ + 512)

__device__ __half g_Wt[(size_t)OUT_DIM * KTOT];   // [n][k] 32 MB

__device__ __forceinline__ uint32_t smem_u32(const void* p) {
    uint32_t a;
    asm("{ .reg .u64 t; cvta.to.shared.u64 t, %1; cvt.u32.u64 %0, t; }" : "=r"(a) : "l"(p));
    return a;
}

// ---------------- kernel 1: transpose + fp16 convert of W ----------------
__global__ void __launch_bounds__(256)
w_prep_kernel(const float* __restrict__ W) {      // W: [KTOT, OUT_DIM]
    __shared__ float t[32][33];
    int k0 = blockIdx.x * 32;
    int n0 = blockIdx.y * 32;
    int tx = threadIdx.x, ty = threadIdx.y;       // block (32, 8)
    #pragma unroll
    for (int r = 0; r < 4; ++r)
        t[ty + 8 * r][tx] = W[(size_t)(k0 + ty + 8 * r) * OUT_DIM + n0 + tx];
    __syncthreads();
    #pragma unroll
    for (int r = 0; r < 4; ++r) {
        float v = t[tx][ty + 8 * r];
        g_Wt[(size_t)(n0 + ty + 8 * r) * KTOT + k0 + tx] = __float2half_rn(v);
    }
}

// ---------------- kernel 2: fused trig-gen + HMMA GEMM (2m x 2n x 2k warps) ----------------
__global__ void __launch_bounds__(THREADS, 1)
fkan_hmma_kernel(const float* __restrict__ X,
                 const float* __restrict__ bias,
                 float* __restrict__ out)
{
    extern __shared__ char smem[];
    const uint32_t sb = smem_u32(smem);
    const int tid = threadIdx.x;
    const int wid = tid >> 5, l = tid & 31;
    const int wk = wid & 1;           // k-half: 0 -> k[0,32), 1 -> k[32,64)
    const int wm = (wid >> 1) & 1;    // m-half: 64 rows
    const int wn = wid >> 2;          // n-half: 64 cols
    const int bn0 = blockIdx.x * BN;
    const int bm0 = blockIdx.y * BM;

    if (tid < BN)
        ((float*)(smem + 2 * STAGE_SZ))[tid] = bias[bn0 + tid];

    // lane-constant ldmatrix address pieces
    const int ar  = ((l >> 3) & 1) * 8 + (l & 7);
    const int akx = (l >> 4) << 4;
    const int br  = ((l >> 4) & 1) * 8 + (l & 7);
    const int bkx = ((l >> 3) & 1) << 4;
    const int sw  = (l & 7) << 4;

    // A-gen: 2 threads per m-row, 16 harmonics each
    const int am = tid >> 1, ah = tid & 1;
    const float* xrow = X + (size_t)(bm0 + am) * IN_DIM;
    // B load: 2 threads per n-row, 64B each
    const int brow = tid >> 1, bhalf = (tid & 1) * 64;
    const char* wsrc0 = (const char*)g_Wt + ((size_t)(bn0 + brow) * KTOT) * 2 + bhalf;

    float acc[4][8][4];
    #pragma unroll
    for (int mf = 0; mf < 4; ++mf)
        #pragma unroll
        for (int nf = 0; nf < 8; ++nf)
            #pragma unroll
            for (int q = 0; q < 4; ++q) acc[mf][nf][q] = 0.f;

    auto fill = [&](int s, int i) {
        const char* src = wsrc0 + (size_t)i * 128;
        uint32_t dst = sb + s * STAGE_SZ + 16384 + brow * 128;
        uint32_t bswz = (brow & 7) << 4;
        #pragma unroll
        for (int j = 0; j < 4; ++j) {
            uint32_t d = dst + ((bhalf + 16 * j) ^ bswz);
            asm volatile("cp.async.cg.shared.global [%0], [%1], 16;"
                         :: "r"(d), "l"(src + 16 * j) : "memory");
        }
        asm volatile("cp.async.commit_group;" ::: "memory");

        float x = xrow[i];
        float s1, c1, cv, sv;
        sincosf(x, &s1, &c1);
        if (ah == 0) { cv = c1; sv = s1; }
        else         { sincosf(17.0f * x, &sv, &cv); }
        uint32_t abase = sb + s * STAGE_SZ + am * 128;
        uint32_t aswz = (am & 7) << 4;
        #pragma unroll
        for (int g = 0; g < 16; ++g) {
            __half2 p = __floats2half2_rn(cv, sv);  // lo=cos, hi=sin
            uint32_t kb = 4 * (ah * 16 + g);
            asm volatile("st.shared.b32 [%0], %1;"
                         :: "r"(abase + (kb ^ aswz)), "r"(*(uint32_t*)&p) : "memory");
            float cn = fmaf(cv, c1, -sv * s1);
            float sn = fmaf(sv, c1,  cv * s1);
            cv = cn; sv = sn;
        }
    };

    auto domma = [&](int s) {
        uint32_t sA = sb + s * STAGE_SZ;
        uint32_t sB = sA + 16384;
        #pragma unroll
        for (int kk = 0; kk < 2; ++kk) {
            const int kbyte = wk * 64 + kk * 32;
            uint32_t a[4][4];
            #pragma unroll
            for (int mf = 0; mf < 4; ++mf) {
                uint32_t addr = sA + (uint32_t)(wm * 64 + mf * 16 + ar) * 128
                              + (uint32_t)((kbyte + akx) ^ sw);
                asm volatile("ldmatrix.sync.aligned.m8n8.x4.shared.b16 {%0,%1,%2,%3}, [%4];"
                    : "=r"(a[mf][0]), "=r"(a[mf][1]), "=r"(a[mf][2]), "=r"(a[mf][3])
                    : "r"(addr));
            }
            uint32_t b[8][2];
            #pragma unroll
            for (int pj = 0; pj < 4; ++pj) {
                uint32_t addr = sB + (uint32_t)(wn * 64 + pj * 16 + br) * 128
                              + (uint32_t)((kbyte + bkx) ^ sw);
                uint32_t r0, r1, r2, r3;
                asm volatile("ldmatrix.sync.aligned.m8n8.x4.shared.b16 {%0,%1,%2,%3}, [%4];"
                    : "=r"(r0), "=r"(r1), "=r"(r2), "=r"(r3) : "r"(addr));
                b[2 * pj][0] = r0;     b[2 * pj][1] = r1;
                b[2 * pj + 1][0] = r2; b[2 * pj + 1][1] = r3;
            }
            #pragma unroll
            for (int mf = 0; mf < 4; ++mf)
                #pragma unroll
                for (int nf = 0; nf < 8; ++nf)
                    asm volatile(
                        "mma.sync.aligned.m16n8k16.row.col.f32.f16.f16.f32 "
                        "{%0,%1,%2,%3}, {%4,%5,%6,%7}, {%8,%9}, {%0,%1,%2,%3};"
                        : "+f"(acc[mf][nf][0]), "+f"(acc[mf][nf][1]),
                          "+f"(acc[mf][nf][2]), "+f"(acc[mf][nf][3])
                        : "r"(a[mf][0]), "r"(a[mf][1]), "r"(a[mf][2]), "r"(a[mf][3]),
                          "r"(b[nf][0]), "r"(b[nf][1]));
        }
    };

    fill(0, 0);
    asm volatile("cp.async.wait_group 0;" ::: "memory");
    __syncthreads();

    for (int i = 0; i < IN_DIM; ++i) {
        const int s = i & 1;
        if (i + 1 < IN_DIM) fill(s ^ 1, i + 1);
        domma(s);
        asm volatile("cp.async.wait_group 0;" ::: "memory");
        __syncthreads();
    }

    // ---- epilogue: k-split reduction through SMEM, + bias, store ----
    // quadrant (wm, wn): 64x64 f32 = 16KB at smem offset (wm*2+wn)*16KB
    float* red = (float*)(smem + (size_t)(wm * 2 + wn) * 16384);
    const int lr = l >> 2, lc = 2 * (l & 3);

    if (wk == 1) {
        #pragma unroll
        for (int mf = 0; mf < 4; ++mf)
            #pragma unroll
            for (int nf = 0; nf < 8; ++nf) {
                int r0 = mf * 16 + lr, c = nf * 8 + lc;
                *(float2*)&red[r0 * 64 + c]       = make_float2(acc[mf][nf][0], acc[mf][nf][1]);
                *(float2*)&red[(r0 + 8) * 64 + c] = make_float2(acc[mf][nf][2], acc[mf][nf][3]);
            }
    }
    __syncthreads();
    if (wk == 0) {
        const float* biasS = (const float*)(smem + 2 * STAGE_SZ);
        #pragma unroll
        for (int mf = 0; mf < 4; ++mf) {
            #pragma unroll
            for (int nf = 0; nf < 8; ++nf) {
                int r0 = mf * 16 + lr, c = nf * 8 + lc;
                int nloc = wn * 64 + c;
                float2 p0 = *(const float2*)&red[r0 * 64 + c];
                float2 p1 = *(const float2*)&red[(r0 + 8) * 64 + c];
                int m0 = bm0 + wm * 64 + r0;
                float2 v0 = { acc[mf][nf][0] + p0.x + biasS[nloc],
                              acc[mf][nf][1] + p0.y + biasS[nloc + 1] };
                float2 v1 = { acc[mf][nf][2] + p1.x + biasS[nloc],
                              acc[mf][nf][3] + p1.y + biasS[nloc + 1] };
                *(float2*)(out + (size_t)m0 * OUT_DIM + bn0 + nloc)       = v0;
                *(float2*)(out + (size_t)(m0 + 8) * OUT_DIM + bn0 + nloc) = v1;
            }
        }
    }
}

// ---------------- launcher ----------------
extern "C" void kernel_launch(void* const* d_in, const int* in_sizes, int n_in,
                              void* d_out, int out_size) {
    const float* X    = (const float*)d_in[0];
    const float* W    = (const float*)d_in[1];
    const float* bias = (const float*)d_in[2];
    float* out = (float*)d_out;
    (void)in_sizes; (void)n_in; (void)out_size;

    dim3 pgrid(KTOT / 32, OUT_DIM / 32);
    w_prep_kernel<<<pgrid, dim3(32, 8)>>>(W);

    cudaFuncSetAttribute(fkan_hmma_kernel,
                         cudaFuncAttributeMaxDynamicSharedMemorySize, SM_TOTAL);
    dim3 grid(OUT_DIM / BN, BATCH / BM);
    fkan_hmma_kernel<<<grid, THREADS, SM_TOTAL>>>(X, bias, out);
}